// round 17
// baseline (speedup 1.0000x reference)
#include <cuda_runtime.h>
#include <cuda_fp16.h>
#include <cstdint>

#define M_TOK 4096
#define HID   4096
#define INTER 11008
#define GRP   64
#define NGK1  (HID / GRP)     // 64
#define NGK2  (INTER / GRP)   // 172

// ---------------------------------------------------------------------------
// Static device scratch (sanctioned mechanism; eager-loaded before checkpoints)
// ---------------------------------------------------------------------------
__device__ __half g_X [(size_t)M_TOK * HID];    //  33.5 MB
__device__ __half g_H [(size_t)M_TOK * INTER];  //  90.2 MB  silu(g)*u
__device__ __half g_Wg[(size_t)INTER * HID];    //  90.2 MB
__device__ __half g_Wu[(size_t)INTER * HID];    //  90.2 MB
__device__ __half g_Wd[(size_t)HID * INTER];    //  90.2 MB

// ---------------------------------------------------------------------------
// PTX helpers (family-portable: sm_75/80-era, safe under compute_103)
// ---------------------------------------------------------------------------
__device__ __forceinline__ uint32_t smem_u32(const void* p) {
    uint32_t a;
    asm("{ .reg .u64 t; cvta.to.shared.u64 t, %1; cvt.u32.u64 %0, t; }" : "=r"(a) : "l"(p));
    return a;
}
__device__ __forceinline__ void cp_async16(uint32_t dst, const void* src) {
    asm volatile("cp.async.cg.shared.global [%0], [%1], 16;" :: "r"(dst), "l"(src));
}
#define CP_COMMIT() asm volatile("cp.async.commit_group;" ::: "memory")
#define CP_WAIT2()  asm volatile("cp.async.wait_group 2;" ::: "memory")

__device__ __forceinline__ void ldsm4(uint32_t* r, uint32_t addr) {
    asm volatile("ldmatrix.sync.aligned.m8n8.x4.shared.b16 {%0,%1,%2,%3}, [%4];"
                 : "=r"(r[0]), "=r"(r[1]), "=r"(r[2]), "=r"(r[3]) : "r"(addr));
}
__device__ __forceinline__ void mma16816(float* d, const uint32_t* a, const uint32_t* b) {
    asm volatile(
        "mma.sync.aligned.m16n8k16.row.col.f32.f16.f16.f32 "
        "{%0,%1,%2,%3},{%4,%5,%6,%7},{%8,%9},{%0,%1,%2,%3};"
        : "+f"(d[0]), "+f"(d[1]), "+f"(d[2]), "+f"(d[3])
        : "r"(a[0]), "r"(a[1]), "r"(a[2]), "r"(a[3]), "r"(b[0]), "r"(b[1]));
}

// BK=32 halfs per row = 64B data, padded to 80B (5x16B chunks; 5 coprime 8 ->
// LDSM 8-row phases hit 8 distinct 16B groups: conflict-free).
#define ROWB 80
#define MLP1_STAGE (2 * 128 * ROWB)     // A + B = 20480 B
#define MLP1_STASH (4 * MLP1_STAGE)     // stash offset = 81920
#define MLP1_SMEM  (4 * MLP1_STAGE + 32768)   // 114688 B -> 2 CTAs/SM (224KB)
#define DN_STAGE (64 * ROWB + 128 * ROWB)     // A(64 rows) + B(128 rows) = 15360 B
#define DN_SMEM  (4 * DN_STAGE)               // 61440 B

// Supertile rasterization: m fastest within a band of SWZ_M m-blocks.
#define SWZ_M 16

// ===========================================================================
// Prep 1: x f32 -> fp16
// ===========================================================================
__global__ void xconv_kernel(const float* __restrict__ X) {
    const size_t i = ((size_t)blockIdx.x * blockDim.x + threadIdx.x) * 4;
    const float4 v = *(const float4*)(X + i);
    const __half2 h0 = __floats2half2_rn(v.x, v.y);
    const __half2 h1 = __floats2half2_rn(v.z, v.w);
    *(uint2*)(g_X + i) = make_uint2(*(const uint32_t*)&h0, *(const uint32_t*)&h1);
}

// ===========================================================================
// Prep 2: int4 -> fp16 dequant (once per weight). hi nibble = even index.
// Exact I2F + fmaf(w, s, -z*s): cancellation-free.
// ===========================================================================
__global__ void dequant_kernel(int sel, const int* __restrict__ Wq,
                               const float* __restrict__ S, const float* __restrict__ Z,
                               int K, int ngk)
{
    const int row = blockIdx.y;
    const int t   = blockIdx.x * blockDim.x + threadIdx.x;
    const int cpr = K / 8;
    if (t >= cpr) return;
    __half* Wh = (sel == 0) ? g_Wg : (sel == 1) ? g_Wu : g_Wd;

    const int4 v = *(const int4*)(Wq + (size_t)row * (K / 2) + t * 4);
    const int g  = (t * 8) / GRP;
    const float s = __ldg(S + (size_t)row * ngk + g);
    const float z = __ldg(Z + (size_t)row * ngk + g);
    const float nzs = -z * s;

    const int vv[4] = {v.x, v.y, v.z, v.w};
    uint32_t out[4];
    #pragma unroll
    for (int j = 0; j < 4; j++) {
        const int b = vv[j];
        const float fh = (float)((b >> 4) & 15);
        const float fl = (float)( b       & 15);
        const __half2 h = __floats2half2_rn(fmaf(fh, s, nzs), fmaf(fl, s, nzs));
        out[j] = *(const uint32_t*)&h;
    }
    *(uint4*)(Wh + (size_t)row * K + t * 8) = make_uint4(out[0], out[1], out[2], out[3]);
}

// ===========================================================================
// GEMM 1 (fused): per CTA tile, run gate GEMM -> stash f16 in SMEM, then up
// GEMM -> silu(g)*u -> g_H. CTA 128x128, BK=32, 8 warps, warp tile 64x32.
// Single accumulator (reused across phases) -> 2 CTAs/SM.
// ===========================================================================
__global__ __launch_bounds__(256, 2)
void mlp1_kernel()
{
    extern __shared__ __align__(128) char dsm[];
    const uint32_t sb = smem_u32(dsm);
    const int tid  = threadIdx.x;
    const int lane = tid & 31;
    const int wid  = tid >> 5;
    const int wm   = (wid & 1) * 64;
    const int wn   = (wid >> 1) * 32;

    constexpr int TN = INTER / 128;           // 86
    const int band = blockIdx.x / (SWZ_M * TN);
    const int rem  = blockIdx.x % (SWZ_M * TN);
    const int m0   = (band * SWZ_M + (rem % SWZ_M)) * 128;
    const int n0   = (rem / SWZ_M) * 128;
    constexpr int NIT = HID / 32;   // 128

    const uint32_t aoff = (uint32_t)((wm + ((lane >> 3) & 1) * 8 + (lane & 7)) * ROWB
                                     + (lane >> 4) * 16);
    const uint32_t boff = (uint32_t)((wn + (lane & 7)) * ROWB + (lane >> 3) * 16);

    float acc[4][4][4];

    auto run_gemm = [&](const __half* Wsrc) {
        #pragma unroll
        for (int i = 0; i < 4; i++)
            #pragma unroll
            for (int j = 0; j < 4; j++)
                #pragma unroll
                for (int k = 0; k < 4; k++) acc[i][j][k] = 0.f;

        auto issue = [&](int it) {
            const int k0 = it * 32;
            const uint32_t st = sb + (it & 3) * MLP1_STAGE;
            #pragma unroll
            for (int p = 0; p < 2; p++) {
                const int cc  = tid + p * 256;
                const int row = cc >> 2, kc = cc & 3;
                const uint32_t d = st + row * ROWB + kc * 16;
                cp_async16(d,         g_X  + (size_t)(m0 + row) * HID + (k0 + kc * 8));
                cp_async16(d + 10240, Wsrc + (size_t)(n0 + row) * HID + (k0 + kc * 8));
            }
        };

        issue(0); CP_COMMIT();
        issue(1); CP_COMMIT();
        issue(2); CP_COMMIT();

        for (int it = 0; it < NIT; ++it) {
            CP_WAIT2();
            __syncthreads();
            if (it + 3 < NIT) issue(it + 3);
            CP_COMMIT();

            const uint32_t Ab = sb + (it & 3) * MLP1_STAGE;
            uint32_t b[4][4];
            #pragma unroll
            for (int nt = 0; nt < 4; nt++)
                ldsm4(b[nt], Ab + 10240 + boff + nt * 8 * ROWB);
            #pragma unroll
            for (int ks = 0; ks < 2; ks++) {
                uint32_t a[4][4];
                #pragma unroll
                for (int mt = 0; mt < 4; mt++)
                    ldsm4(a[mt], Ab + aoff + mt * 16 * ROWB + ks * 32);
                #pragma unroll
                for (int mt = 0; mt < 4; mt++)
                    #pragma unroll
                    for (int nt = 0; nt < 4; nt++)
                        mma16816(acc[mt][nt], a[mt], &b[nt][ks * 2]);
            }
        }
    };

    // ---- phase 0: gate -> SMEM stash (f16), idx-major (conflict-free) ----
    run_gemm(g_Wg);
    #pragma unroll
    for (int mt = 0; mt < 4; mt++)
        #pragma unroll
        for (int rr = 0; rr < 2; rr++)
            #pragma unroll
            for (int nt = 0; nt < 4; nt++) {
                const int idx = (mt * 2 + rr) * 4 + nt;
                const __half2 h = __floats2half2_rn(acc[mt][nt][rr * 2 + 0],
                                                    acc[mt][nt][rr * 2 + 1]);
                *(__half2*)(dsm + MLP1_STASH + idx * 1024 + tid * 4) = h;
            }
    // No sync needed: each thread reads back only its own stash slots, and
    // phase-1's first CP_WAIT2+__syncthreads orders stage-buffer reuse.

    // ---- phase 1: up; epilogue fuses silu(g)*u -> g_H ----
    run_gemm(g_Wu);
    const int r = lane >> 2, c = lane & 3;
    #pragma unroll
    for (int mt = 0; mt < 4; mt++)
        #pragma unroll
        for (int rr = 0; rr < 2; rr++) {
            const int row = m0 + wm + mt * 16 + r + rr * 8;
            #pragma unroll
            for (int nt = 0; nt < 4; nt++) {
                const int col = n0 + wn + nt * 8 + 2 * c;
                const int idx = (mt * 2 + rr) * 4 + nt;
                const __half2 gh = *(const __half2*)(dsm + MLP1_STASH + idx * 1024 + tid * 4);
                const float2 gf = __half22float2(gh);
                const float u0 = acc[mt][nt][rr * 2 + 0];
                const float u1 = acc[mt][nt][rr * 2 + 1];
                const float h0 = gf.x / (1.f + __expf(-gf.x)) * u0;
                const float h1 = gf.y / (1.f + __expf(-gf.y)) * u1;
                *(__half2*)(g_H + (size_t)row * INTER + col) = __floats2half2_rn(h0, h1);
            }
        }
}

// ===========================================================================
// GEMM 2: down. CTA 64x128 (2048 tiles -> 7 waves, was 4 partials of 3.46),
// BK=32, 8 warps 2(m)x4(n), warp tile 32x32, fp32 output. 2+ CTAs/SM.
// ===========================================================================
__global__ __launch_bounds__(256, 2)
void down_kernel(float* __restrict__ Out)
{
    extern __shared__ __align__(128) char dsm[];
    const uint32_t sb = smem_u32(dsm);
    const int tid  = threadIdx.x;
    const int lane = tid & 31;
    const int wid  = tid >> 5;
    const int wm   = (wid & 1) * 32;
    const int wn   = (wid >> 1) * 32;

    constexpr int TN = HID / 128;             // 32
    const int band = blockIdx.x / (SWZ_M * TN);
    const int rem  = blockIdx.x % (SWZ_M * TN);
    const int m0   = (band * SWZ_M + (rem % SWZ_M)) * 64;
    const int n0   = (rem / SWZ_M) * 128;
    constexpr int NIT = INTER / 32;   // 344

    const uint32_t aoff = (uint32_t)((wm + ((lane >> 3) & 1) * 8 + (lane & 7)) * ROWB
                                     + (lane >> 4) * 16);
    const uint32_t boff = (uint32_t)((wn + (lane & 7)) * ROWB + (lane >> 3) * 16);
    constexpr uint32_t BOFF0 = 64 * ROWB;   // B starts after 64 A rows

    float acc[2][4][4];
    #pragma unroll
    for (int i = 0; i < 2; i++)
        #pragma unroll
        for (int j = 0; j < 4; j++)
            #pragma unroll
            for (int k = 0; k < 4; k++) acc[i][j][k] = 0.f;

    auto issue = [&](int it) {
        const int k0 = it * 32;
        const uint32_t st = sb + (it & 3) * DN_STAGE;
        {   // A: 64 rows x 4 chunks = 256
            const int row = tid >> 2, kc = tid & 3;
            cp_async16(st + row * ROWB + kc * 16,
                       g_H + (size_t)(m0 + row) * INTER + (k0 + kc * 8));
        }
        #pragma unroll
        for (int p = 0; p < 2; p++) {   // B: 128 rows x 4 chunks = 512
            const int cc  = tid + p * 256;
            const int row = cc >> 2, kc = cc & 3;
            cp_async16(st + BOFF0 + row * ROWB + kc * 16,
                       g_Wd + (size_t)(n0 + row) * INTER + (k0 + kc * 8));
        }
    };

    issue(0); CP_COMMIT();
    issue(1); CP_COMMIT();
    issue(2); CP_COMMIT();

    for (int it = 0; it < NIT; ++it) {
        CP_WAIT2();
        __syncthreads();
        if (it + 3 < NIT) issue(it + 3);
        CP_COMMIT();

        const uint32_t Ab = sb + (it & 3) * DN_STAGE;
        uint32_t b[4][4];
        #pragma unroll
        for (int nt = 0; nt < 4; nt++)
            ldsm4(b[nt], Ab + BOFF0 + boff + nt * 8 * ROWB);
        #pragma unroll
        for (int ks = 0; ks < 2; ks++) {
            uint32_t a[2][4];
            #pragma unroll
            for (int mt = 0; mt < 2; mt++)
                ldsm4(a[mt], Ab + aoff + mt * 16 * ROWB + ks * 32);
            #pragma unroll
            for (int mt = 0; mt < 2; mt++)
                #pragma unroll
                for (int nt = 0; nt < 4; nt++)
                    mma16816(acc[mt][nt], a[mt], &b[nt][ks * 2]);
        }
    }

    const int r = lane >> 2, c = lane & 3;
    #pragma unroll
    for (int mt = 0; mt < 2; mt++)
        #pragma unroll
        for (int rr = 0; rr < 2; rr++) {
            const int row = m0 + wm + mt * 16 + r + rr * 8;
            #pragma unroll
            for (int nt = 0; nt < 4; nt++) {
                const int col = n0 + wn + nt * 8 + 2 * c;
                *(float2*)(Out + (size_t)row * HID + col) =
                    make_float2(acc[mt][nt][rr * 2 + 0], acc[mt][nt][rr * 2 + 1]);
            }
        }
}

// ===========================================================================
// Eager init: force module load (~395MB globals) + smem attrs, before the
// harness's tracked mem-checkpoint window. (Eager load fixed R5-R7.)
// ===========================================================================
namespace {
struct ForceModuleLoad {
    ForceModuleLoad() {
        void* p = nullptr;
        (void)cudaGetSymbolAddress(&p, g_H);
        (void)cudaFuncSetAttribute(mlp1_kernel,
                                   cudaFuncAttributeMaxDynamicSharedMemorySize, MLP1_SMEM);
        (void)cudaFuncSetAttribute(down_kernel,
                                   cudaFuncAttributeMaxDynamicSharedMemorySize, DN_SMEM);
    }
};
static ForceModuleLoad g_force_module_load;
}

// ===========================================================================
extern "C" void kernel_launch(void* const* d_in, const int* in_sizes, int n_in,
                              void* d_out, int out_size)
{
    const float* x  = (const float*)d_in[0];
    const int*   gw = (const int*)  d_in[1];
    const int*   uw = (const int*)  d_in[2];
    const int*   dw = (const int*)  d_in[3];
    const float* gs = (const float*)d_in[4];
    const float* gz = (const float*)d_in[5];
    const float* us = (const float*)d_in[6];
    const float* uz = (const float*)d_in[7];
    const float* ds = (const float*)d_in[8];
    const float* dz = (const float*)d_in[9];
    float* out = (float*)d_out;

    // Prep: x -> fp16, weights -> fp16 (one-time per launch)
    xconv_kernel<<<(M_TOK * HID) / (256 * 4), 256>>>(x);
    dequant_kernel<<<dim3(4,  INTER), 128>>>(0, gw, gs, gz, HID,   NGK1);
    dequant_kernel<<<dim3(4,  INTER), 128>>>(1, uw, us, uz, HID,   NGK1);
    dequant_kernel<<<dim3(11, HID),   128>>>(2, dw, ds, dz, INTER, NGK2);

    dim3 blk(256);
    mlp1_kernel<<<(INTER / 128) * (M_TOK / 128), blk, MLP1_SMEM>>>();  // 2752 CTAs
    down_kernel<<<(HID / 128) * (M_TOK / 64), blk, DN_SMEM>>>(out);    // 2048 CTAs
}